// round 15
// baseline (speedup 1.0000x reference)
#include <cuda_runtime.h>
#include <cuda_fp16.h>
#include <cstdint>

// SparseConv1D as 32 shifted GEMMs via mma.sync fp16 (single term).
// R15: 3-slot B pipeline (prefetch distance 2, wait_group 1), chunked window
// fill overlapping early taps, prep_zero merged into prep_x.

#define LEN 4096
#define CIN 64
#define COUT 64
#define BATCH 16
#define K_TAPS 32
#define PADLEN 4864
#define THREADS 512
#define WROWS 1280
#define RSTRIDE 144
#define WINBYTES (WROWS * RSTRIDE)          // 184320
#define BSM_BYTES (3 * 8192)
#define SMEM_BYTES (WINBYTES + BSM_BYTES)   // 208896

__device__ __align__(16) __half g_x[(size_t)BATCH * PADLEN * CIN];
__device__ __align__(16) uint2 g_wf[K_TAPS * 4 * 8 * 32];   // [tap][k][nt][lane]

__constant__ int c_sk[K_TAPS] = {
    -512,-256,-128,-96,-64,-48,-32,-24,-16,-12,-8,-6,-4,-3,-2,-1,
     0,1,2,3,4,6,8,12,16,24,32,48,64,96,128,256
};

__device__ __forceinline__ unsigned smem_u32(const void* p) {
    unsigned a;
    asm("{ .reg .u64 t; cvta.to.shared.u64 t, %1; cvt.u32.u64 %0, t; }"
        : "=r"(a) : "l"(p));
    return a;
}
__device__ __forceinline__ void cp16(unsigned d, const void* s) {
    asm volatile("cp.async.cg.shared.global [%0], [%1], 16;" :: "r"(d), "l"(s));
}
__device__ __forceinline__ void cpc()  { asm volatile("cp.async.commit_group;"); }
__device__ __forceinline__ void cpw0() { asm volatile("cp.async.wait_group 0;"); }
__device__ __forceinline__ void cpw1() { asm volatile("cp.async.wait_group 1;"); }
__device__ __forceinline__ void cpw2() { asm volatile("cp.async.wait_group 2;"); }
__device__ __forceinline__ void ldmA(unsigned* r, unsigned addr) {
    asm volatile("ldmatrix.sync.aligned.m8n8.x4.shared.b16 {%0,%1,%2,%3}, [%4];"
        : "=r"(r[0]), "=r"(r[1]), "=r"(r[2]), "=r"(r[3]) : "r"(addr));
}
__device__ __forceinline__ void mma16816(float* d, const unsigned* a, uint2 b) {
    asm volatile(
        "mma.sync.aligned.m16n8k16.row.col.f32.f16.f16.f32 "
        "{%0,%1,%2,%3}, {%4,%5,%6,%7}, {%8,%9}, {%0,%1,%2,%3};"
        : "+f"(d[0]), "+f"(d[1]), "+f"(d[2]), "+f"(d[3])
        : "r"(a[0]), "r"(a[1]), "r"(a[2]), "r"(a[3]), "r"(b.x), "r"(b.y));
}
__device__ __forceinline__ unsigned pk(__half a, __half b) {
    __half2 t(a, b);
    return *reinterpret_cast<unsigned*>(&t);
}

// ---- prepass: transpose x -> [b][pos][ch] fp16 + zero pads (merged) ----
__global__ __launch_bounds__(512) void prep_x(const float* __restrict__ x) {
    const int bx = blockIdx.x, b = blockIdx.y, tid = threadIdx.x;
    if (bx >= 64) {            // pad-zero blocks: 12 blocks x 64 rows = 768 rows
        int r = (bx - 64) * 64 + (tid >> 3);
        int pp = (r < 512) ? r : r + 4096;
        *reinterpret_cast<uint4*>(
            g_x + ((size_t)b * PADLEN + pp) * CIN + (tid & 7) * 8) =
            make_uint4(0, 0, 0, 0);
        return;
    }
    __shared__ float tile[64][65];
    const int p0 = bx * 64;
#pragma unroll
    for (int it = 0; it < 8; ++it) {
        int e = tid + it * 512;
        int ch = e >> 6, pos = e & 63;
        tile[ch][pos] = x[((size_t)b * CIN + ch) * LEN + p0 + pos];
    }
    __syncthreads();
    const int j = tid & 7, pp = tid >> 3;
    __half h[8];
#pragma unroll
    for (int c = 0; c < 8; ++c) h[c] = __float2half(tile[j * 8 + c][pp]);
    size_t off = ((size_t)b * PADLEN + 512 + p0 + pp) * CIN + j * 8;
    *reinterpret_cast<uint4*>(g_x + off) =
        make_uint4(pk(h[0],h[1]), pk(h[2],h[3]), pk(h[4],h[5]), pk(h[6],h[7]));
}

__global__ void prep_w(const float* __restrict__ w) {
    int idx = blockIdx.x * blockDim.x + threadIdx.x;
    if (idx >= K_TAPS * 4 * 8 * 32) return;
    int lane = idx & 31, nt = (idx >> 5) & 7, kt = (idx >> 8) & 3, t = idx >> 10;
    int n = nt * 8 + (lane >> 2);
    int k = kt * 16 + (lane & 3) * 2;
    __half h0 = __float2half(w[((size_t)n * CIN + k)     * K_TAPS + t]);
    __half h1 = __float2half(w[((size_t)n * CIN + k + 1) * K_TAPS + t]);
    __half h8 = __float2half(w[((size_t)n * CIN + k + 8) * K_TAPS + t]);
    __half h9 = __float2half(w[((size_t)n * CIN + k + 9) * K_TAPS + t]);
    g_wf[((size_t)t * 4 + kt) * 256 + nt * 32 + lane] =
        make_uint2(pk(h0, h1), pk(h8, h9));
}

// ---- main kernel ----
struct Ctx {
    unsigned win_s, bsm_s;
    const uint2* bsm;
    int wid, lane, lrow, lcolb, tid;
};

__device__ __forceinline__ void ldaS(const Ctx& c, unsigned (&a)[2][4], int s) {
    const int rowb = c.wid * 32 + c_sk[s >> 2] + 512;
    const int k = s & 3;
    const unsigned base =
        c.win_s + (unsigned)((rowb + c.lrow) * RSTRIDE + k * 32 + c.lcolb);
    ldmA(a[0], base);
    ldmA(a[1], base + 16 * RSTRIDE);
}
__device__ __forceinline__ void loadBsm(const Ctx& c, const uint2* bb,
                                        uint2 (&b)[4], int k, int h) {
    const uint2* p = bb + k * 256 + h * 128 + c.lane;
#pragma unroll
    for (int i = 0; i < 4; ++i) b[i] = p[i * 32];
}

__global__ __launch_bounds__(THREADS, 1)
void conv_mma(float* __restrict__ out) {
    extern __shared__ __align__(16) char smem[];
    const int tid = threadIdx.x, wid = tid >> 5, lane = tid & 31;
    const int st = blockIdx.x, b = blockIdx.y;
    const int P0 = st * 512;

    Ctx c;
    c.win_s = smem_u32(smem);
    c.bsm_s = c.win_s + WINBYTES;
    c.bsm   = reinterpret_cast<const uint2*>(smem + WINBYTES);
    c.wid = wid; c.lane = lane; c.tid = tid;
    c.lrow = lane & 15;
    c.lcolb = ((lane >> 4) * 8) * 2;

    float acc[2][8][4];
#pragma unroll
    for (int mt = 0; mt < 2; ++mt)
#pragma unroll
        for (int n = 0; n < 8; ++n)
#pragma unroll
            for (int q = 0; q < 4; ++q) acc[mt][n][q] = 0.f;

    const __half* base = g_x + ((size_t)b * PADLEN + P0) * CIN;
    const char* wsrc = (const char*)g_wf;

    // G1: window rows [0,1024) — needed by taps with d<=0 (t<=16)
#pragma unroll
    for (int it = 0; it < 16; ++it) {
        int cc = tid + it * THREADS;          // 8192 chunks
        int row = cc >> 3, ch = cc & 7;
        cp16(c.win_s + row * RSTRIDE + ch * 16, base + row * CIN + ch * 8);
    }
    cpc();
    // G2: B tap0 -> slot 0
    cp16(c.bsm_s + tid * 16, wsrc + tid * 16);
    cpc();
    // G3: window rows [1024,1280) — needed from t=17; overlaps early taps
#pragma unroll
    for (int it = 0; it < 4; ++it) {
        int cc = 8192 + tid + it * THREADS;   // 2048 chunks
        int row = cc >> 3, ch = cc & 7;
        cp16(c.win_s + row * RSTRIDE + ch * 16, base + row * CIN + ch * 8);
    }
    cpc();
    // G4: B tap1 -> slot 1
    cp16(c.bsm_s + 8192 + tid * 16, wsrc + 8192 + tid * 16);
    cpc();

    cpw2();                 // G1,G2 done; G3,G4 in flight
    __syncthreads();

    unsigned a[2][2][4];
    uint2 bf[2][4];
    ldaS(c, a[0], 0);
    loadBsm(c, c.bsm, bf[0], 0, 0);

    for (int t = 0; t < K_TAPS; ++t) {
        const int slot = t % 3;
        const uint2* bb = c.bsm + slot * 1024;
        if (t + 2 < K_TAPS) {       // prefetch distance 2
            const int ds = (t + 2) % 3;
            cp16(c.bsm_s + ds * 8192 + tid * 16,
                 wsrc + (size_t)(t + 2) * 8192 + tid * 16);
            cpc();
        }
#pragma unroll
        for (int k = 0; k < 4; ++k) {
            const int s = t * 4 + k;
            unsigned (&aC)[2][4] = a[k & 1];
            unsigned (&aN)[2][4] = a[(k + 1) & 1];
#pragma unroll
            for (int u = 0; u < 2; ++u) {
                const int m = k * 2 + u;
                uint2 (&cur)[4] = bf[m & 1];
                uint2 (&nxt)[4] = bf[(m + 1) & 1];
                if (u == 0 && s + 1 < 4 * K_TAPS) ldaS(c, aN, s + 1);
                if (m + 1 < 8) loadBsm(c, bb, nxt, (m + 1) >> 1, (m + 1) & 1);
#pragma unroll
                for (int i = 0; i < 4; ++i)
#pragma unroll
                    for (int mt = 0; mt < 2; ++mt)
                        mma16816(acc[mt][u * 4 + i], aC[mt], cur[i]);
            }
        }
        if (t + 2 < K_TAPS) cpw1();   // B(t+1) ready, B(t+2) may pend
        else cpw0();
        __syncthreads();
        if (t + 1 < K_TAPS)
            loadBsm(c, c.bsm + ((t + 1) % 3) * 1024, bf[0], 0, 0);
    }

    // ---- store D fragments ----
    const int g = lane >> 2, c0 = (lane & 3) * 2;
#pragma unroll
    for (int mt = 0; mt < 2; ++mt) {
        const int pos = P0 + wid * 32 + mt * 16 + g;
#pragma unroll
        for (int n = 0; n < 8; ++n) {
            const int o = n * 8 + c0;
            float* q0 = out + ((size_t)b * COUT + o) * LEN;
            float* q1 = out + ((size_t)b * COUT + o + 1) * LEN;
            q0[pos]     = acc[mt][n][0];
            q1[pos]     = acc[mt][n][1];
            q0[pos + 8] = acc[mt][n][2];
            q1[pos + 8] = acc[mt][n][3];
        }
    }
}

extern "C" void kernel_launch(void* const* d_in, const int* in_sizes, int n_in,
                              void* d_out, int out_size) {
    const float* x = (const float*)d_in[0];
    const float* w = (const float*)d_in[1];
    float* out = (float*)d_out;

    prep_x<<<dim3(76, BATCH), 512>>>(x);       // transpose + pad zeros merged
    prep_w<<<(K_TAPS * 4 * 8 * 32 + 255) / 256, 256>>>(w);

    cudaFuncSetAttribute(conv_mma, cudaFuncAttributeMaxDynamicSharedMemorySize,
                         SMEM_BYTES);
    conv_mma<<<dim3(8, BATCH), THREADS, SMEM_BYTES>>>(out);
}

// round 16
// speedup vs baseline: 1.0361x; 1.0361x over previous
#include <cuda_runtime.h>
#include <cuda_fp16.h>
#include <cstdint>

// SparseConv1D as 32 shifted GEMMs via mma.sync fp16 (single term).
// R16: R14's proven pipeline at 2-tap granularity (16 barriers, 16KB B copies
// covered by ~2 taps of compute), float4-vectorized transpose prepass.

#define LEN 4096
#define CIN 64
#define COUT 64
#define BATCH 16
#define K_TAPS 32
#define PADLEN 4864
#define THREADS 512
#define WROWS 1280
#define RSTRIDE 144
#define WINBYTES (WROWS * RSTRIDE)          // 184320
#define BSM_BYTES (4 * 8192)                // two 16KB pair-slots
#define SMEM_BYTES (WINBYTES + BSM_BYTES)   // 217088

__device__ __align__(16) __half g_x[(size_t)BATCH * PADLEN * CIN];
__device__ __align__(16) uint2 g_wf[K_TAPS * 4 * 8 * 32];   // [tap][k][nt][lane]

__constant__ int c_sk[K_TAPS] = {
    -512,-256,-128,-96,-64,-48,-32,-24,-16,-12,-8,-6,-4,-3,-2,-1,
     0,1,2,3,4,6,8,12,16,24,32,48,64,96,128,256
};

__device__ __forceinline__ unsigned smem_u32(const void* p) {
    unsigned a;
    asm("{ .reg .u64 t; cvta.to.shared.u64 t, %1; cvt.u32.u64 %0, t; }"
        : "=r"(a) : "l"(p));
    return a;
}
__device__ __forceinline__ void cp16(unsigned d, const void* s) {
    asm volatile("cp.async.cg.shared.global [%0], [%1], 16;" :: "r"(d), "l"(s));
}
__device__ __forceinline__ void cpc()  { asm volatile("cp.async.commit_group;"); }
__device__ __forceinline__ void cpw0() { asm volatile("cp.async.wait_group 0;"); }
__device__ __forceinline__ void ldmA(unsigned* r, unsigned addr) {
    asm volatile("ldmatrix.sync.aligned.m8n8.x4.shared.b16 {%0,%1,%2,%3}, [%4];"
        : "=r"(r[0]), "=r"(r[1]), "=r"(r[2]), "=r"(r[3]) : "r"(addr));
}
__device__ __forceinline__ void mma16816(float* d, const unsigned* a, uint2 b) {
    asm volatile(
        "mma.sync.aligned.m16n8k16.row.col.f32.f16.f16.f32 "
        "{%0,%1,%2,%3}, {%4,%5,%6,%7}, {%8,%9}, {%0,%1,%2,%3};"
        : "+f"(d[0]), "+f"(d[1]), "+f"(d[2]), "+f"(d[3])
        : "r"(a[0]), "r"(a[1]), "r"(a[2]), "r"(a[3]), "r"(b.x), "r"(b.y));
}
__device__ __forceinline__ unsigned pk(__half a, __half b) {
    __half2 t(a, b);
    return *reinterpret_cast<unsigned*>(&t);
}

// ---- prepass: transpose x -> [b][pos][ch] fp16 + zero pads (merged) ----
__global__ __launch_bounds__(512) void prep_x(const float* __restrict__ x) {
    const int bx = blockIdx.x, b = blockIdx.y, tid = threadIdx.x;
    if (bx >= 64) {            // pad-zero blocks: 12 blocks x 64 rows
        int r = (bx - 64) * 64 + (tid >> 3);
        int pp = (r < 512) ? r : r + 4096;
        *reinterpret_cast<uint4*>(
            g_x + ((size_t)b * PADLEN + pp) * CIN + (tid & 7) * 8) =
            make_uint4(0, 0, 0, 0);
        return;
    }
    __shared__ float tile[64][68];
    const int p0 = bx * 64;
#pragma unroll
    for (int it = 0; it < 2; ++it) {          // 1024 float4 loads
        int e = tid + it * 512;
        int ch = e >> 4, pos4 = (e & 15) * 4;
        float4 v = *reinterpret_cast<const float4*>(
            x + ((size_t)b * CIN + ch) * LEN + p0 + pos4);
        tile[ch][pos4]     = v.x;
        tile[ch][pos4 + 1] = v.y;
        tile[ch][pos4 + 2] = v.z;
        tile[ch][pos4 + 3] = v.w;
    }
    __syncthreads();
    const int j = tid & 7, pp = tid >> 3;
    __half h[8];
#pragma unroll
    for (int c = 0; c < 8; ++c) h[c] = __float2half(tile[j * 8 + c][pp]);
    size_t off = ((size_t)b * PADLEN + 512 + p0 + pp) * CIN + j * 8;
    *reinterpret_cast<uint4*>(g_x + off) =
        make_uint4(pk(h[0],h[1]), pk(h[2],h[3]), pk(h[4],h[5]), pk(h[6],h[7]));
}

__global__ void prep_w(const float* __restrict__ w) {
    int idx = blockIdx.x * blockDim.x + threadIdx.x;
    if (idx >= K_TAPS * 4 * 8 * 32) return;
    int lane = idx & 31, nt = (idx >> 5) & 7, kt = (idx >> 8) & 3, t = idx >> 10;
    int n = nt * 8 + (lane >> 2);
    int k = kt * 16 + (lane & 3) * 2;
    __half h0 = __float2half(w[((size_t)n * CIN + k)     * K_TAPS + t]);
    __half h1 = __float2half(w[((size_t)n * CIN + k + 1) * K_TAPS + t]);
    __half h8 = __float2half(w[((size_t)n * CIN + k + 8) * K_TAPS + t]);
    __half h9 = __float2half(w[((size_t)n * CIN + k + 9) * K_TAPS + t]);
    g_wf[((size_t)t * 4 + kt) * 256 + nt * 32 + lane] =
        make_uint2(pk(h0, h1), pk(h8, h9));
}

// ---- main kernel ----
struct Ctx {
    unsigned win_s, bsm_s;
    const uint2* bsm;
    int wid, lane, lrow, lcolb, tid;
};

__device__ __forceinline__ void ldaS(const Ctx& c, unsigned (&a)[2][4], int s) {
    const int rowb = c.wid * 32 + c_sk[s >> 2] + 512;
    const int k = s & 3;
    const unsigned base =
        c.win_s + (unsigned)((rowb + c.lrow) * RSTRIDE + k * 32 + c.lcolb);
    ldmA(a[0], base);
    ldmA(a[1], base + 16 * RSTRIDE);
}
// m in [0,16): tap-in-pair = m>>3, k = (m>>1)&3, n-half = m&1
__device__ __forceinline__ void loadBsm(const Ctx& c, const uint2* pairb,
                                        uint2 (&b)[4], int m) {
    const uint2* p = pairb + (m >> 3) * 1024 + ((m >> 1) & 3) * 256
                     + (m & 1) * 128 + c.lane;
#pragma unroll
    for (int i = 0; i < 4; ++i) b[i] = p[i * 32];
}

__global__ __launch_bounds__(THREADS, 1)
void conv_mma(float* __restrict__ out) {
    extern __shared__ __align__(16) char smem[];
    const int tid = threadIdx.x, wid = tid >> 5, lane = tid & 31;
    const int st = blockIdx.x, b = blockIdx.y;
    const int P0 = st * 512;

    Ctx c;
    c.win_s = smem_u32(smem);
    c.bsm_s = c.win_s + WINBYTES;
    c.bsm   = reinterpret_cast<const uint2*>(smem + WINBYTES);
    c.wid = wid; c.lane = lane; c.tid = tid;
    c.lrow = lane & 15;
    c.lcolb = ((lane >> 4) * 8) * 2;

    float acc[2][8][4];
#pragma unroll
    for (int mt = 0; mt < 2; ++mt)
#pragma unroll
        for (int n = 0; n < 8; ++n)
#pragma unroll
            for (int q = 0; q < 4; ++q) acc[mt][n][q] = 0.f;

    // ---- fill window + B pair 0 (taps 0,1 -> slot half 0) ----
    const __half* base = g_x + ((size_t)b * PADLEN + P0) * CIN;
#pragma unroll
    for (int it = 0; it < (WROWS * 8) / THREADS; ++it) {
        int cc = tid + it * THREADS;
        int row = cc >> 3, ch = cc & 7;
        cp16(c.win_s + row * RSTRIDE + ch * 16, base + row * CIN + ch * 8);
    }
    const char* wsrc = (const char*)g_wf;
#pragma unroll
    for (int q = 0; q < 2; ++q) {
        int cc = tid + q * THREADS;
        cp16(c.bsm_s + cc * 16, wsrc + cc * 16);
    }
    cpc(); cpw0();
    __syncthreads();

    unsigned a[2][2][4];
    uint2 bf[2][4];
    ldaS(c, a[0], 0);
    loadBsm(c, c.bsm, bf[0], 0);

    for (int tt = 0; tt < K_TAPS / 2; ++tt) {
        const int half = tt & 1;
        const uint2* pairb = c.bsm + half * 2048;   // 16 KB = 2048 uint2
        if (tt + 1 < K_TAPS / 2) {    // async next tap-pair into other half
            const char* src = wsrc + (size_t)(tt + 1) * 16384;
            const unsigned dst = c.bsm_s + (half ^ 1) * 16384;
#pragma unroll
            for (int q = 0; q < 2; ++q) {
                int cc = tid + q * THREADS;
                cp16(dst + cc * 16, src + cc * 16);
            }
            cpc();
        }
#pragma unroll
        for (int m = 0; m < 16; ++m) {        // 2 taps x 4 k x 2 n-halves
            const int s = tt * 8 + (m >> 1);  // global k-step index
            unsigned (&aC)[2][4] = a[(m >> 1) & 1];
            unsigned (&aN)[2][4] = a[((m >> 1) + 1) & 1];
            uint2 (&cur)[4] = bf[m & 1];
            uint2 (&nxt)[4] = bf[(m + 1) & 1];
            if ((m & 1) == 0 && s + 1 < 4 * K_TAPS) ldaS(c, aN, s + 1);
            if (m + 1 < 16) loadBsm(c, pairb, nxt, m + 1);
            const int h = m & 1;
#pragma unroll
            for (int i = 0; i < 4; ++i)
#pragma unroll
                for (int mt = 0; mt < 2; ++mt)
                    mma16816(acc[mt][h * 4 + i], aC[mt], cur[i]);
        }
        cpw0();
        __syncthreads();
        if (tt + 1 < K_TAPS / 2)
            loadBsm(c, c.bsm + (half ^ 1) * 2048, bf[0], 0);
    }

    // ---- store D fragments ----
    const int g = lane >> 2, c0 = (lane & 3) * 2;
#pragma unroll
    for (int mt = 0; mt < 2; ++mt) {
        const int pos = P0 + wid * 32 + mt * 16 + g;
#pragma unroll
        for (int n = 0; n < 8; ++n) {
            const int o = n * 8 + c0;
            float* q0 = out + ((size_t)b * COUT + o) * LEN;
            float* q1 = out + ((size_t)b * COUT + o + 1) * LEN;
            q0[pos]     = acc[mt][n][0];
            q1[pos]     = acc[mt][n][1];
            q0[pos + 8] = acc[mt][n][2];
            q1[pos + 8] = acc[mt][n][3];
        }
    }
}

extern "C" void kernel_launch(void* const* d_in, const int* in_sizes, int n_in,
                              void* d_out, int out_size) {
    const float* x = (const float*)d_in[0];
    const float* w = (const float*)d_in[1];
    float* out = (float*)d_out;

    prep_x<<<dim3(76, BATCH), 512>>>(x);
    prep_w<<<(K_TAPS * 4 * 8 * 32 + 255) / 256, 256>>>(w);

    cudaFuncSetAttribute(conv_mma, cudaFuncAttributeMaxDynamicSharedMemorySize,
                         SMEM_BYTES);
    conv_mma<<<dim3(8, BATCH), THREADS, SMEM_BYTES>>>(out);
}

// round 17
// speedup vs baseline: 1.0833x; 1.0456x over previous
#include <cuda_runtime.h>
#include <cuda_fp16.h>
#include <cstdint>

// SparseConv1D as 32 shifted GEMMs via mma.sync fp16 (single term).
// R17: R16's 2-tap-granularity mma pipeline (proven ~44us) + R15's scalar
// transpose prepass (proven ~8us) + weight packing merged into the same
// prepass launch (2 kernels total).

#define LEN 4096
#define CIN 64
#define COUT 64
#define BATCH 16
#define K_TAPS 32
#define PADLEN 4864
#define THREADS 512
#define WROWS 1280
#define RSTRIDE 144
#define WINBYTES (WROWS * RSTRIDE)          // 184320
#define BSM_BYTES (4 * 8192)                // two 16KB pair-slots
#define SMEM_BYTES (WINBYTES + BSM_BYTES)   // 217088

__device__ __align__(16) __half g_x[(size_t)BATCH * PADLEN * CIN];
__device__ __align__(16) uint2 g_wf[K_TAPS * 4 * 8 * 32];   // [tap][k][nt][lane]

__constant__ int c_sk[K_TAPS] = {
    -512,-256,-128,-96,-64,-48,-32,-24,-16,-12,-8,-6,-4,-3,-2,-1,
     0,1,2,3,4,6,8,12,16,24,32,48,64,96,128,256
};

__device__ __forceinline__ unsigned smem_u32(const void* p) {
    unsigned a;
    asm("{ .reg .u64 t; cvta.to.shared.u64 t, %1; cvt.u32.u64 %0, t; }"
        : "=r"(a) : "l"(p));
    return a;
}
__device__ __forceinline__ void cp16(unsigned d, const void* s) {
    asm volatile("cp.async.cg.shared.global [%0], [%1], 16;" :: "r"(d), "l"(s));
}
__device__ __forceinline__ void cpc()  { asm volatile("cp.async.commit_group;"); }
__device__ __forceinline__ void cpw0() { asm volatile("cp.async.wait_group 0;"); }
__device__ __forceinline__ void ldmA(unsigned* r, unsigned addr) {
    asm volatile("ldmatrix.sync.aligned.m8n8.x4.shared.b16 {%0,%1,%2,%3}, [%4];"
        : "=r"(r[0]), "=r"(r[1]), "=r"(r[2]), "=r"(r[3]) : "r"(addr));
}
__device__ __forceinline__ void mma16816(float* d, const unsigned* a, uint2 b) {
    asm volatile(
        "mma.sync.aligned.m16n8k16.row.col.f32.f16.f16.f32 "
        "{%0,%1,%2,%3}, {%4,%5,%6,%7}, {%8,%9}, {%0,%1,%2,%3};"
        : "+f"(d[0]), "+f"(d[1]), "+f"(d[2]), "+f"(d[3])
        : "r"(a[0]), "r"(a[1]), "r"(a[2]), "r"(a[3]), "r"(b.x), "r"(b.y));
}
__device__ __forceinline__ unsigned pk(__half a, __half b) {
    __half2 t(a, b);
    return *reinterpret_cast<unsigned*>(&t);
}

// ---- single prepass: x transpose (bx<64) + pad zeros (64<=bx<76)
//                      + weight fragment packing (bx>=76) ----
__global__ __launch_bounds__(512) void prep_all(const float* __restrict__ x,
                                                const float* __restrict__ w) {
    const int bx = blockIdx.x, b = blockIdx.y, tid = threadIdx.x;

    if (bx >= 76) {            // weight packing: 4x16 blocks x 512 = 32768
        int idx = ((bx - 76) * 16 + b) * 512 + tid;
        int lane = idx & 31, nt = (idx >> 5) & 7, kt = (idx >> 8) & 3,
            t = idx >> 10;
        int n = nt * 8 + (lane >> 2);
        int k = kt * 16 + (lane & 3) * 2;
        __half h0 = __float2half(w[((size_t)n * CIN + k)     * K_TAPS + t]);
        __half h1 = __float2half(w[((size_t)n * CIN + k + 1) * K_TAPS + t]);
        __half h8 = __float2half(w[((size_t)n * CIN + k + 8) * K_TAPS + t]);
        __half h9 = __float2half(w[((size_t)n * CIN + k + 9) * K_TAPS + t]);
        g_wf[((size_t)t * 4 + kt) * 256 + nt * 32 + lane] =
            make_uint2(pk(h0, h1), pk(h8, h9));
        return;
    }
    if (bx >= 64) {            // pad-zero blocks: 12 blocks x 64 rows
        int r = (bx - 64) * 64 + (tid >> 3);
        int pp = (r < 512) ? r : r + 4096;
        *reinterpret_cast<uint4*>(
            g_x + ((size_t)b * PADLEN + pp) * CIN + (tid & 7) * 8) =
            make_uint4(0, 0, 0, 0);
        return;
    }
    // transpose tile (scalar loads — R15-proven fastest variant)
    __shared__ float tile[64][65];
    const int p0 = bx * 64;
#pragma unroll
    for (int it = 0; it < 8; ++it) {
        int e = tid + it * 512;
        int ch = e >> 6, pos = e & 63;
        tile[ch][pos] = x[((size_t)b * CIN + ch) * LEN + p0 + pos];
    }
    __syncthreads();
    const int j = tid & 7, pp = tid >> 3;
    __half h[8];
#pragma unroll
    for (int c = 0; c < 8; ++c) h[c] = __float2half(tile[j * 8 + c][pp]);
    size_t off = ((size_t)b * PADLEN + 512 + p0 + pp) * CIN + j * 8;
    *reinterpret_cast<uint4*>(g_x + off) =
        make_uint4(pk(h[0],h[1]), pk(h[2],h[3]), pk(h[4],h[5]), pk(h[6],h[7]));
}

// ---- main kernel (R16 2-tap pipeline, verbatim) ----
struct Ctx {
    unsigned win_s, bsm_s;
    const uint2* bsm;
    int wid, lane, lrow, lcolb, tid;
};

__device__ __forceinline__ void ldaS(const Ctx& c, unsigned (&a)[2][4], int s) {
    const int rowb = c.wid * 32 + c_sk[s >> 2] + 512;
    const int k = s & 3;
    const unsigned base =
        c.win_s + (unsigned)((rowb + c.lrow) * RSTRIDE + k * 32 + c.lcolb);
    ldmA(a[0], base);
    ldmA(a[1], base + 16 * RSTRIDE);
}
// m in [0,16): tap-in-pair = m>>3, k = (m>>1)&3, n-half = m&1
__device__ __forceinline__ void loadBsm(const Ctx& c, const uint2* pairb,
                                        uint2 (&b)[4], int m) {
    const uint2* p = pairb + (m >> 3) * 1024 + ((m >> 1) & 3) * 256
                     + (m & 1) * 128 + c.lane;
#pragma unroll
    for (int i = 0; i < 4; ++i) b[i] = p[i * 32];
}

__global__ __launch_bounds__(THREADS, 1)
void conv_mma(float* __restrict__ out) {
    extern __shared__ __align__(16) char smem[];
    const int tid = threadIdx.x, wid = tid >> 5, lane = tid & 31;
    const int st = blockIdx.x, b = blockIdx.y;
    const int P0 = st * 512;

    Ctx c;
    c.win_s = smem_u32(smem);
    c.bsm_s = c.win_s + WINBYTES;
    c.bsm   = reinterpret_cast<const uint2*>(smem + WINBYTES);
    c.wid = wid; c.lane = lane; c.tid = tid;
    c.lrow = lane & 15;
    c.lcolb = ((lane >> 4) * 8) * 2;

    float acc[2][8][4];
#pragma unroll
    for (int mt = 0; mt < 2; ++mt)
#pragma unroll
        for (int n = 0; n < 8; ++n)
#pragma unroll
            for (int q = 0; q < 4; ++q) acc[mt][n][q] = 0.f;

    // ---- fill window + B pair 0 ----
    const __half* base = g_x + ((size_t)b * PADLEN + P0) * CIN;
#pragma unroll
    for (int it = 0; it < (WROWS * 8) / THREADS; ++it) {
        int cc = tid + it * THREADS;
        int row = cc >> 3, ch = cc & 7;
        cp16(c.win_s + row * RSTRIDE + ch * 16, base + row * CIN + ch * 8);
    }
    const char* wsrc = (const char*)g_wf;
#pragma unroll
    for (int q = 0; q < 2; ++q) {
        int cc = tid + q * THREADS;
        cp16(c.bsm_s + cc * 16, wsrc + cc * 16);
    }
    cpc(); cpw0();
    __syncthreads();

    unsigned a[2][2][4];
    uint2 bf[2][4];
    ldaS(c, a[0], 0);
    loadBsm(c, c.bsm, bf[0], 0);

    for (int tt = 0; tt < K_TAPS / 2; ++tt) {
        const int half = tt & 1;
        const uint2* pairb = c.bsm + half * 2048;
        if (tt + 1 < K_TAPS / 2) {
            const char* src = wsrc + (size_t)(tt + 1) * 16384;
            const unsigned dst = c.bsm_s + (half ^ 1) * 16384;
#pragma unroll
            for (int q = 0; q < 2; ++q) {
                int cc = tid + q * THREADS;
                cp16(dst + cc * 16, src + cc * 16);
            }
            cpc();
        }
#pragma unroll
        for (int m = 0; m < 16; ++m) {
            const int s = tt * 8 + (m >> 1);
            unsigned (&aC)[2][4] = a[(m >> 1) & 1];
            unsigned (&aN)[2][4] = a[((m >> 1) + 1) & 1];
            uint2 (&cur)[4] = bf[m & 1];
            uint2 (&nxt)[4] = bf[(m + 1) & 1];
            if ((m & 1) == 0 && s + 1 < 4 * K_TAPS) ldaS(c, aN, s + 1);
            if (m + 1 < 16) loadBsm(c, pairb, nxt, m + 1);
            const int h = m & 1;
#pragma unroll
            for (int i = 0; i < 4; ++i)
#pragma unroll
                for (int mt = 0; mt < 2; ++mt)
                    mma16816(acc[mt][h * 4 + i], aC[mt], cur[i]);
        }
        cpw0();
        __syncthreads();
        if (tt + 1 < K_TAPS / 2)
            loadBsm(c, c.bsm + (half ^ 1) * 2048, bf[0], 0);
    }

    // ---- store D fragments ----
    const int g = lane >> 2, c0 = (lane & 3) * 2;
#pragma unroll
    for (int mt = 0; mt < 2; ++mt) {
        const int pos = P0 + wid * 32 + mt * 16 + g;
#pragma unroll
        for (int n = 0; n < 8; ++n) {
            const int o = n * 8 + c0;
            float* q0 = out + ((size_t)b * COUT + o) * LEN;
            float* q1 = out + ((size_t)b * COUT + o + 1) * LEN;
            q0[pos]     = acc[mt][n][0];
            q1[pos]     = acc[mt][n][1];
            q0[pos + 8] = acc[mt][n][2];
            q1[pos + 8] = acc[mt][n][3];
        }
    }
}

extern "C" void kernel_launch(void* const* d_in, const int* in_sizes, int n_in,
                              void* d_out, int out_size) {
    const float* x = (const float*)d_in[0];
    const float* w = (const float*)d_in[1];
    float* out = (float*)d_out;

    prep_all<<<dim3(80, BATCH), 512>>>(x, w);   // transpose + pads + weights

    cudaFuncSetAttribute(conv_mma, cudaFuncAttributeMaxDynamicSharedMemorySize,
                         SMEM_BYTES);
    conv_mma<<<dim3(8, BATCH), THREADS, SMEM_BYTES>>>(out);
}